// round 1
// baseline (speedup 1.0000x reference)
#include <cuda_runtime.h>

// Problem constants (fixed by setup_inputs)
#define BB 8
#define NN 1024
#define KNN 8
#define MPTS (BB * NN)        // 8192 points total
#define MBIG (MPTS * KNN)     // 65536 grouped rows

// ---------------- scratch (static device globals; no allocation allowed) ----
__device__ float g_U[MPTS * 1024];
__device__ float g_V[MPTS * 1024];
__device__ float g_Y[(size_t)MBIG * 1024];
__device__ float g_Z[(size_t)MBIG * 1024];
__device__ float g_l0[MPTS * 512];
__device__ float g_wd[1024 * 512];
__device__ int   g_idx[MPTS * KNN];
__device__ float g_scale[1024];
__device__ float g_shift[1024];
__device__ float g_ps[1024];
__device__ float g_ps2[1024];

// ---------------- SGEMM: C[m,n] = sum_k A[m*lda+k] * B[n*ldb+k] --------------
// 128x128 block tile, 8x8 per-thread microtile, K-tile 8. Guards on M/N/K edges.
__global__ void sgemm_nt(const float* __restrict__ A, int lda,
                         const float* __restrict__ Bw, int ldb,
                         float* __restrict__ C, int M, int K, int Ncol) {
    __shared__ float As[8][128];
    __shared__ float Bs[8][128];
    const int tid = threadIdx.x;
    const int m0 = blockIdx.y * 128;
    const int n0 = blockIdx.x * 128;
    const int tx = tid % 16;
    const int ty = tid / 16;

    float acc[8][8];
#pragma unroll
    for (int i = 0; i < 8; i++)
#pragma unroll
        for (int j = 0; j < 8; j++) acc[i][j] = 0.f;

    const int lm = tid >> 1;          // 0..127 row within tile
    const int lk = (tid & 1) * 4;     // 0 or 4

    for (int k0 = 0; k0 < K; k0 += 8) {
#pragma unroll
        for (int i = 0; i < 4; i++) {
            int kk = lk + i;
            int gm = m0 + lm, gk = k0 + kk;
            float v = 0.f;
            if (gm < M && gk < K) v = A[(long)gm * lda + gk];
            As[kk][lm] = v;
        }
#pragma unroll
        for (int i = 0; i < 4; i++) {
            int kk = lk + i;
            int gn = n0 + lm, gk = k0 + kk;
            float v = 0.f;
            if (gn < Ncol && gk < K) v = Bw[(long)gn * ldb + gk];
            Bs[kk][lm] = v;
        }
        __syncthreads();
#pragma unroll
        for (int kk = 0; kk < 8; kk++) {
            float a[8], b[8];
#pragma unroll
            for (int i = 0; i < 8; i++) a[i] = As[kk][ty * 8 + i];
#pragma unroll
            for (int j = 0; j < 8; j++) b[j] = Bs[kk][tx * 8 + j];
#pragma unroll
            for (int i = 0; i < 8; i++)
#pragma unroll
                for (int j = 0; j < 8; j++) acc[i][j] += a[i] * b[j];
        }
        __syncthreads();
    }

#pragma unroll
    for (int i = 0; i < 8; i++) {
        int gm = m0 + ty * 8 + i;
        if (gm >= M) continue;
#pragma unroll
        for (int j = 0; j < 8; j++) {
            int gn = n0 + tx * 8 + j;
            if (gn < Ncol) C[(long)gm * Ncol + gn] = acc[i][j];
        }
    }
}

// ---------------- BatchNorm (training-mode stats over all rows) --------------
__global__ void zero2(float* a, float* b, int n) {
    int i = blockIdx.x * blockDim.x + threadIdx.x;
    if (i < n) { a[i] = 0.f; b[i] = 0.f; }
}

// grid: (C/32, 32 row-chunks), block (32, 8). Coalesced along channels.
__global__ void bn_stats_partial(const float* __restrict__ X, int M, int C,
                                 float* __restrict__ psum, float* __restrict__ psum2) {
    int c = blockIdx.x * 32 + threadIdx.x;
    int rows_per = (M + gridDim.y - 1) / gridDim.y;
    int m0 = blockIdx.y * rows_per;
    int m1 = m0 + rows_per; if (m1 > M) m1 = M;
    float s = 0.f, s2 = 0.f;
    for (int m = m0 + threadIdx.y; m < m1; m += 8) {
        float v = X[(long)m * C + c];
        s += v; s2 += v * v;
    }
    __shared__ float sh[8][32], sh2[8][32];
    sh[threadIdx.y][threadIdx.x] = s;
    sh2[threadIdx.y][threadIdx.x] = s2;
    __syncthreads();
    if (threadIdx.y == 0) {
#pragma unroll
        for (int r = 1; r < 8; r++) { s += sh[r][threadIdx.x]; s2 += sh2[r][threadIdx.x]; }
        atomicAdd(&psum[c], s);
        atomicAdd(&psum2[c], s2);
    }
}

__global__ void bn_finalize(int M, int C,
                            const float* __restrict__ psum, const float* __restrict__ psum2,
                            const float* __restrict__ gamma, const float* __restrict__ beta,
                            float* __restrict__ scale, float* __restrict__ shift) {
    int c = blockIdx.x * blockDim.x + threadIdx.x;
    if (c >= C) return;
    float mean = psum[c] / (float)M;
    float var = psum2[c] / (float)M - mean * mean;
    float sc = gamma[c] * rsqrtf(var + 1e-5f);
    scale[c] = sc;
    shift[c] = beta[c] - mean * sc;
}

// x <- relu(x*scale[c] + shift[c]), in place, float4-vectorized
__global__ void bn_apply_relu(float* __restrict__ X, long total4, int C4,
                              const float* __restrict__ scale, const float* __restrict__ shift) {
    long i = (long)blockIdx.x * blockDim.x + threadIdx.x;
    if (i >= total4) return;
    int c4 = (int)(i % C4) * 4;
    float4 v = ((float4*)X)[i];
    v.x = fmaxf(v.x * scale[c4 + 0] + shift[c4 + 0], 0.f);
    v.y = fmaxf(v.y * scale[c4 + 1] + shift[c4 + 1], 0.f);
    v.z = fmaxf(v.z * scale[c4 + 2] + shift[c4 + 2], 0.f);
    v.w = fmaxf(v.w * scale[c4 + 3] + shift[c4 + 3], 0.f);
    ((float4*)X)[i] = v;
}

// ---------------- kNN (k=8 incl. self), per-batch in shared memory ----------
__global__ void knn_kernel(const float* __restrict__ xyz, int* __restrict__ idx) {
    int b = blockIdx.x;
    __shared__ float sx[NN], sy[NN], sz[NN];
    const float* base = xyz + (long)b * NN * 3;
    for (int i = threadIdx.x; i < NN; i += blockDim.x) {
        sx[i] = base[i * 3 + 0];
        sy[i] = base[i * 3 + 1];
        sz[i] = base[i * 3 + 2];
    }
    __syncthreads();
    for (int q = threadIdx.x; q < NN; q += blockDim.x) {
        float qx = sx[q], qy = sy[q], qz = sz[q];
        float bd[KNN]; int bi[KNN];
#pragma unroll
        for (int t = 0; t < KNN; t++) { bd[t] = 3.0e38f; bi[t] = 0; }
        for (int j = 0; j < NN; j++) {
            float dx = sx[j] - qx, dy = sy[j] - qy, dz = sz[j] - qz;
            float d = dx * dx + dy * dy + dz * dz;
            if (d < bd[KNN - 1]) {
                int p = KNN - 1;
#pragma unroll
                for (int t = 0; t < KNN - 1; t++) {
                    if (p > 0 && d < bd[p - 1]) { bd[p] = bd[p - 1]; bi[p] = bi[p - 1]; p--; }
                }
                bd[p] = d; bi[p] = j;
            }
        }
#pragma unroll
        for (int t = 0; t < KNN; t++) idx[(b * NN + q) * KNN + t] = bi[t];
    }
}

// ---------------- y[b,n,k,:] = U[b, idx[b,n,k], :] + V[b,n,:] ----------------
__global__ void gather_add(const float* __restrict__ U, const float* __restrict__ V,
                           const int* __restrict__ idx, float* __restrict__ Y, int C) {
    int C4 = C >> 2;
    long total = (long)MBIG * C4;
    long i = (long)blockIdx.x * blockDim.x + threadIdx.x;
    if (i >= total) return;
    int c4 = (int)(i % C4);
    long r = i / C4;               // grouped row: (b*NN + n)*KNN + k
    long bn = r >> 3;              // b*NN + n
    int b = (int)(bn >> 10);
    int j = idx[r];                // neighbor index within batch
    float4 u = ((const float4*)U)[((long)(b * NN + j)) * C4 + c4];
    float4 v = ((const float4*)V)[bn * C4 + c4];
    float4 o; o.x = u.x + v.x; o.y = u.y + v.y; o.z = u.z + v.z; o.w = u.w + v.w;
    ((float4*)Y)[i] = o;
}

// wd[o, d] = W[o, Ck + d] - W[o, d]   (W is (O, 2*Ck) row-major)
__global__ void wdiff_kernel(const float* __restrict__ W, float* __restrict__ wd,
                             int O, int Ck) {
    long total = (long)O * Ck;
    long i = (long)blockIdx.x * blockDim.x + threadIdx.x;
    if (i >= total) return;
    int o = (int)(i / Ck), d = (int)(i % Ck);
    wd[i] = W[(long)o * 2 * Ck + Ck + d] - W[(long)o * 2 * Ck + d];
}

// out[bn, c] = max_k Z[(bn*8+k), c]
__global__ void max_over_k(const float* __restrict__ Z, float* __restrict__ O, int C) {
    long total = (long)MPTS * C;
    long i = (long)blockIdx.x * blockDim.x + threadIdx.x;
    if (i >= total) return;
    int c = (int)(i % C);
    long r = i / C;
    const float* p = Z + r * KNN * (long)C + c;
    float m = p[0];
#pragma unroll
    for (int k = 1; k < KNN; k++) m = fmaxf(m, p[(long)k * C]);
    O[i] = m;
}

// out[(b*C + c)*NN + n] = max_k Z[((b*NN+n)*8+k), c]   (final transpose)
__global__ void max_over_k_t(const float* __restrict__ Z, float* __restrict__ O, int C) {
    long total = (long)MPTS * C;
    long i = (long)blockIdx.x * blockDim.x + threadIdx.x;
    if (i >= total) return;
    int c = (int)(i % C);
    long r = i / C;                 // b*NN + n
    int b = (int)(r >> 10);
    int n = (int)(r & (NN - 1));
    const float* p = Z + r * KNN * (long)C + c;
    float m = p[0];
#pragma unroll
    for (int k = 1; k < KNN; k++) m = fmaxf(m, p[(long)k * C]);
    O[((long)b * C + c) * NN + n] = m;
}

// ---------------- host orchestration ----------------------------------------
extern "C" void kernel_launch(void* const* d_in, const int* in_sizes, int n_in,
                              void* d_out, int out_size) {
    const float* xyz = (const float*)d_in[0];
    const float* W1  = (const float*)d_in[1];
    const float* g1  = (const float*)d_in[2];
    const float* b1  = (const float*)d_in[3];
    const float* W2  = (const float*)d_in[4];
    const float* g2  = (const float*)d_in[5];
    const float* b2  = (const float*)d_in[6];
    const float* WA1 = (const float*)d_in[7];
    const float* gA1 = (const float*)d_in[8];
    const float* bA1 = (const float*)d_in[9];
    const float* WA2 = (const float*)d_in[10];
    const float* gA2 = (const float*)d_in[11];
    const float* bA2 = (const float*)d_in[12];
    const float* WB1 = (const float*)d_in[13];
    const float* gB1 = (const float*)d_in[14];
    const float* bB1 = (const float*)d_in[15];
    const float* WB2 = (const float*)d_in[16];
    const float* gB2 = (const float*)d_in[17];
    const float* bB2 = (const float*)d_in[18];
    float* out = (float*)d_out;

    float *U, *V, *Y, *Z, *l0, *wd, *scale, *shift, *ps, *ps2;
    int* idx;
    cudaGetSymbolAddress((void**)&U, g_U);
    cudaGetSymbolAddress((void**)&V, g_V);
    cudaGetSymbolAddress((void**)&Y, g_Y);
    cudaGetSymbolAddress((void**)&Z, g_Z);
    cudaGetSymbolAddress((void**)&l0, g_l0);
    cudaGetSymbolAddress((void**)&wd, g_wd);
    cudaGetSymbolAddress((void**)&idx, g_idx);
    cudaGetSymbolAddress((void**)&scale, g_scale);
    cudaGetSymbolAddress((void**)&shift, g_shift);
    cudaGetSymbolAddress((void**)&ps, g_ps);
    cudaGetSymbolAddress((void**)&ps2, g_ps2);

    auto gemm = [&](const float* A, int lda, const float* Bw, int ldb,
                    float* Cm, int M, int K, int Nc) {
        dim3 gs((Nc + 127) / 128, (M + 127) / 128);
        sgemm_nt<<<gs, 256>>>(A, lda, Bw, ldb, Cm, M, K, Nc);
    };
    auto run_bn = [&](float* X, int M, int C, const float* gm, const float* bt) {
        zero2<<<(C + 255) / 256, 256>>>(ps, ps2, C);
        dim3 bs(32, 8), gs(C / 32, 32);
        bn_stats_partial<<<gs, bs>>>(X, M, C, ps, ps2);
        bn_finalize<<<(C + 255) / 256, 256>>>(M, C, ps, ps2, gm, bt, scale, shift);
        long total4 = (long)M * C / 4;
        bn_apply_relu<<<(unsigned)((total4 + 255) / 256), 256>>>(X, total4, C / 4, scale, shift);
    };

    // Layer 1: (8192,3) @ W1(64,3)^T -> Y; BN+relu in place.  h1 lives in Y.
    gemm(xyz, 3, W1, 3, Y, MPTS, 3, 64);
    run_bn(Y, MPTS, 64, g1, b1);
    // Layer 2: h1 @ W2(256,64)^T -> Z; BN+relu.  h2 lives in Z.
    gemm(Y, 64, W2, 64, Z, MPTS, 64, 256);
    run_bn(Z, MPTS, 256, g2, b2);

    // kNN indices (k=8, includes self)
    knn_kernel<<<BB, 256>>>(xyz, idx);

    // ---- local_op A (C_in=256 per half, WA1/WA2 512x512) ----
    // U = h2 @ WA1[:, :256]^T ; V = h2 @ (WA1[:,256:] - WA1[:,:256])^T
    wdiff_kernel<<<(512 * 256 + 255) / 256, 256>>>(WA1, wd, 512, 256);
    gemm(Z, 256, WA1, 512, U, MPTS, 256, 512);
    gemm(Z, 256, wd, 256, V, MPTS, 256, 512);
    {
        long t4 = (long)MBIG * 512 / 4;
        gather_add<<<(unsigned)((t4 + 255) / 256), 256>>>(U, V, idx, Y, 512);
    }
    run_bn(Y, MBIG, 512, gA1, bA1);
    gemm(Y, 512, WA2, 512, Z, MBIG, 512, 512);
    run_bn(Z, MBIG, 512, gA2, bA2);
    {
        long t = (long)MPTS * 512;
        max_over_k<<<(unsigned)((t + 255) / 256), 256>>>(Z, l0, 512);
    }

    // ---- local_op B (C_in=512 per half, WB1/WB2 1024x1024) ----
    wdiff_kernel<<<(1024 * 512 + 255) / 256, 256>>>(WB1, wd, 1024, 512);
    gemm(l0, 512, WB1, 1024, U, MPTS, 512, 1024);
    gemm(l0, 512, wd, 512, V, MPTS, 512, 1024);
    {
        long t4 = (long)MBIG * 1024 / 4;
        gather_add<<<(unsigned)((t4 + 255) / 256), 256>>>(U, V, idx, Y, 1024);
    }
    run_bn(Y, MBIG, 1024, gB1, bB1);
    gemm(Y, 1024, WB2, 1024, Z, MBIG, 1024, 1024);
    run_bn(Z, MBIG, 1024, gB2, bB2);
    {
        long t = (long)MPTS * 1024;
        max_over_k_t<<<(unsigned)((t + 255) / 256), 256>>>(Z, out, 1024);
    }
}

// round 5
// speedup vs baseline: 3.7825x; 3.7825x over previous
#include <cuda_runtime.h>
#include <cuda_bf16.h>
#include <cstdint>

// Problem constants (fixed by setup_inputs)
#define BB 8
#define NN 1024
#define KNN 8
#define MPTS (BB * NN)        // 8192 points
#define MBIG (MPTS * KNN)     // 65536 grouped rows

// ---------------- scratch (static device globals) ---------------------------
__device__ float g_U[MPTS * 1024];
__device__ float g_V[MPTS * 1024];
__device__ float g_Y[(size_t)MBIG * 1024];
__device__ float g_Z[(size_t)MBIG * 1024];
__device__ __nv_bfloat16 g_aH[(size_t)MBIG * 1024];
__device__ __nv_bfloat16 g_aL[(size_t)MBIG * 1024];
__device__ __nv_bfloat16 g_wH[1024 * 1024];
__device__ __nv_bfloat16 g_wL[1024 * 1024];
__device__ int   g_idx[MPTS * KNN];
__device__ float g_scale[1024];
__device__ float g_shift[1024];
__device__ float g_ps[1024];
__device__ float g_ps2[1024];

// ======================= helpers =============================================
__device__ __forceinline__ uint32_t smem_u32(const void* p) {
    uint32_t a;
    asm("{ .reg .u64 t; cvta.to.shared.u64 t, %1; cvt.u32.u64 %0, t; }" : "=r"(a) : "l"(p));
    return a;
}

__device__ __forceinline__ void ldsm_x4(uint32_t* r, uint32_t addr) {
    asm volatile("ldmatrix.sync.aligned.m8n8.x4.shared.b16 {%0,%1,%2,%3}, [%4];"
                 : "=r"(r[0]), "=r"(r[1]), "=r"(r[2]), "=r"(r[3]) : "r"(addr));
}

__device__ __forceinline__ void mma16816(float* d, const uint32_t* a, uint32_t b0, uint32_t b1) {
    asm volatile(
        "mma.sync.aligned.m16n8k16.row.col.f32.bf16.bf16.f32 "
        "{%0,%1,%2,%3}, {%4,%5,%6,%7}, {%8,%9}, {%0,%1,%2,%3};"
        : "+f"(d[0]), "+f"(d[1]), "+f"(d[2]), "+f"(d[3])
        : "r"(a[0]), "r"(a[1]), "r"(a[2]), "r"(a[3]), "r"(b0), "r"(b1));
}

// ======================= bf16x3 MMA GEMM =====================================
// C[m,n] = sum_k A[m,k]*B[n,k] via AhBh + AlBh + AhBl (bf16 hi/lo splits).
// 128x128 CTA tile, 8 warps (4x2) of 32x64, BK=32, 3-stage cp.async pipeline.
// SMEM rows: 64B (32 bf16); swizzle: 16B-chunk c -> c ^ ((row>>1)&3).
__global__ void __launch_bounds__(256) gemm_mma(
    const __nv_bfloat16* __restrict__ Ah, const __nv_bfloat16* __restrict__ Al,
    const __nv_bfloat16* __restrict__ Bh, const __nv_bfloat16* __restrict__ Bl,
    float* __restrict__ C, int M, int K, int Ncol)
{
    __shared__ __align__(16) unsigned char smem[3 * 16384];   // per stage: A 8KB + B 8KB
    const int tid = threadIdx.x;
    const int wid = tid >> 5, lane = tid & 31;
    const int m0 = blockIdx.y * 128, n0 = blockIdx.x * 128;
    const int warp_m = (wid & 3) * 32;
    const int warp_n = (wid >> 2) * 64;
    const uint32_t sbase = smem_u32(smem);

    float acc[2][8][4];
#pragma unroll
    for (int i = 0; i < 2; i++)
#pragma unroll
        for (int j = 0; j < 8; j++)
#pragma unroll
            for (int q = 0; q < 4; q++) acc[i][j][q] = 0.f;

    const int nch = 3 * (K >> 5);

    auto stage_issue = [&](int g, int s) {
        const __nv_bfloat16* A_;
        const __nv_bfloat16* B_;
        int ka;
        int kk = g * 32;
        if (kk < K)          { A_ = Ah; B_ = Bh; ka = kk; }
        else if (kk < 2 * K) { A_ = Al; B_ = Bh; ka = kk - K; }
        else                 { A_ = Ah; B_ = Bl; ka = kk - 2 * K; }
        int row = tid >> 2;         // 0..63
        int c = tid & 3;            // 16B chunk
#pragma unroll
        for (int h = 0; h < 2; h++) {
            int r = row + h * 64;
            uint32_t soff = (uint32_t)(s * 16384 + r * 64 + ((c ^ ((r >> 1) & 3)) * 16));
            const void* gp = A_ + (size_t)(m0 + r) * K + ka + c * 8;
            asm volatile("cp.async.cg.shared.global [%0], [%1], 16;" :: "r"(sbase + soff), "l"(gp));
        }
#pragma unroll
        for (int h = 0; h < 2; h++) {
            int r = row + h * 64;
            uint32_t soff = (uint32_t)(s * 16384 + 8192 + r * 64 + ((c ^ ((r >> 1) & 3)) * 16));
            const void* gp = B_ + (size_t)(n0 + r) * K + ka + c * 8;
            asm volatile("cp.async.cg.shared.global [%0], [%1], 16;" :: "r"(sbase + soff), "l"(gp));
        }
        asm volatile("cp.async.commit_group;");
    };

    stage_issue(0, 0);
    if (nch > 1) stage_issue(1, 1);

    for (int g = 0; g < nch; g++) {
        if (g == nch - 1) asm volatile("cp.async.wait_group 0;" ::: "memory");
        else              asm volatile("cp.async.wait_group 1;" ::: "memory");
        __syncthreads();
        if (g + 2 < nch) stage_issue(g + 2, (g + 2) % 3);

        const int s = g % 3;
        const uint32_t sA = sbase + s * 16384;
        const uint32_t sB = sA + 8192;
#pragma unroll
        for (int ks = 0; ks < 2; ks++) {
            uint32_t a[2][4], b[4][4];
#pragma unroll
            for (int mi = 0; mi < 2; mi++) {
                int r = warp_m + mi * 16 + (lane & 15);
                int ch = ks * 2 + (lane >> 4);
                ldsm_x4(a[mi], sA + r * 64 + ((ch ^ ((r >> 1) & 3)) * 16));
            }
#pragma unroll
            for (int nj = 0; nj < 4; nj++) {
                int r = warp_n + nj * 16 + ((lane >> 4) & 1) * 8 + (lane & 7);
                int ch = ks * 2 + ((lane >> 3) & 1);
                ldsm_x4(b[nj], sB + r * 64 + ((ch ^ ((r >> 1) & 3)) * 16));
            }
#pragma unroll
            for (int mi = 0; mi < 2; mi++)
#pragma unroll
                for (int nj = 0; nj < 4; nj++) {
                    mma16816(acc[mi][nj * 2 + 0], a[mi], b[nj][0], b[nj][1]);
                    mma16816(acc[mi][nj * 2 + 1], a[mi], b[nj][2], b[nj][3]);
                }
        }
    }

    // epilogue: d frag rows l/4 (+8), cols 2*(l%4)
#pragma unroll
    for (int mi = 0; mi < 2; mi++) {
        int rbase = m0 + warp_m + mi * 16 + (lane >> 2);
#pragma unroll
        for (int ni = 0; ni < 8; ni++) {
            int col = n0 + warp_n + ni * 8 + 2 * (lane & 3);
            float2 v0 = make_float2(acc[mi][ni][0], acc[mi][ni][1]);
            float2 v1 = make_float2(acc[mi][ni][2], acc[mi][ni][3]);
            *(float2*)&C[(size_t)rbase * Ncol + col] = v0;
            *(float2*)&C[(size_t)(rbase + 8) * Ncol + col] = v1;
        }
    }
}

// ======================= fp32 SGEMM (small layers only) ======================
__global__ void sgemm_nt(const float* __restrict__ A, int lda,
                         const float* __restrict__ Bw, int ldb,
                         float* __restrict__ C, int M, int K, int Ncol) {
    __shared__ float As[8][128];
    __shared__ float Bs[8][128];
    const int tid = threadIdx.x;
    const int m0 = blockIdx.y * 128;
    const int n0 = blockIdx.x * 128;
    const int tx = tid % 16;
    const int ty = tid / 16;
    float acc[8][8];
#pragma unroll
    for (int i = 0; i < 8; i++)
#pragma unroll
        for (int j = 0; j < 8; j++) acc[i][j] = 0.f;
    const int lm = tid >> 1;
    const int lk = (tid & 1) * 4;
    for (int k0 = 0; k0 < K; k0 += 8) {
#pragma unroll
        for (int i = 0; i < 4; i++) {
            int kk = lk + i;
            int gm = m0 + lm, gk = k0 + kk;
            float v = 0.f;
            if (gm < M && gk < K) v = A[(long)gm * lda + gk];
            As[kk][lm] = v;
        }
#pragma unroll
        for (int i = 0; i < 4; i++) {
            int kk = lk + i;
            int gn = n0 + lm, gk = k0 + kk;
            float v = 0.f;
            if (gn < Ncol && gk < K) v = Bw[(long)gn * ldb + gk];
            Bs[kk][lm] = v;
        }
        __syncthreads();
#pragma unroll
        for (int kk = 0; kk < 8; kk++) {
            float a[8], b[8];
#pragma unroll
            for (int i = 0; i < 8; i++) a[i] = As[kk][ty * 8 + i];
#pragma unroll
            for (int j = 0; j < 8; j++) b[j] = Bs[kk][tx * 8 + j];
#pragma unroll
            for (int i = 0; i < 8; i++)
#pragma unroll
                for (int j = 0; j < 8; j++) acc[i][j] += a[i] * b[j];
        }
        __syncthreads();
    }
#pragma unroll
    for (int i = 0; i < 8; i++) {
        int gm = m0 + ty * 8 + i;
        if (gm >= M) continue;
#pragma unroll
        for (int j = 0; j < 8; j++) {
            int gn = n0 + tx * 8 + j;
            if (gn < Ncol) C[(long)gm * Ncol + gn] = acc[i][j];
        }
    }
}

// ======================= BatchNorm pieces ====================================
__global__ void zero2(float* a, float* b, int n) {
    int i = blockIdx.x * blockDim.x + threadIdx.x;
    if (i < n) { a[i] = 0.f; b[i] = 0.f; }
}

__global__ void bn_stats_partial(const float* __restrict__ X, int M, int C,
                                 float* __restrict__ psum, float* __restrict__ psum2) {
    int c = blockIdx.x * 32 + threadIdx.x;
    int rows_per = (M + gridDim.y - 1) / gridDim.y;
    int m0 = blockIdx.y * rows_per;
    int m1 = m0 + rows_per; if (m1 > M) m1 = M;
    float s = 0.f, s2 = 0.f;
    for (int m = m0 + threadIdx.y; m < m1; m += 8) {
        float v = X[(long)m * C + c];
        s += v; s2 += v * v;
    }
    __shared__ float sh[8][32], sh2[8][32];
    sh[threadIdx.y][threadIdx.x] = s;
    sh2[threadIdx.y][threadIdx.x] = s2;
    __syncthreads();
    if (threadIdx.y == 0) {
#pragma unroll
        for (int r = 1; r < 8; r++) { s += sh[r][threadIdx.x]; s2 += sh2[r][threadIdx.x]; }
        atomicAdd(&psum[c], s);
        atomicAdd(&psum2[c], s2);
    }
}

__global__ void bn_finalize(int M, int C,
                            const float* __restrict__ psum, const float* __restrict__ psum2,
                            const float* __restrict__ gamma, const float* __restrict__ beta,
                            float* __restrict__ scale, float* __restrict__ shift) {
    int c = blockIdx.x * blockDim.x + threadIdx.x;
    if (c >= C) return;
    float mean = psum[c] / (float)M;
    float var = psum2[c] / (float)M - mean * mean;
    float sc = gamma[c] * rsqrtf(var + 1e-5f);
    scale[c] = sc;
    shift[c] = beta[c] - mean * sc;
}

// fp32 in-place apply (layer-1 only)
__global__ void bn_apply_relu(float* __restrict__ X, long total4, int C4,
                              const float* __restrict__ scale, const float* __restrict__ shift) {
    long i = (long)blockIdx.x * blockDim.x + threadIdx.x;
    if (i >= total4) return;
    int c4 = (int)(i % C4) * 4;
    float4 v = ((float4*)X)[i];
    v.x = fmaxf(v.x * scale[c4 + 0] + shift[c4 + 0], 0.f);
    v.y = fmaxf(v.y * scale[c4 + 1] + shift[c4 + 1], 0.f);
    v.z = fmaxf(v.z * scale[c4 + 2] + shift[c4 + 2], 0.f);
    v.w = fmaxf(v.w * scale[c4 + 3] + shift[c4 + 3], 0.f);
    ((float4*)X)[i] = v;
}

__device__ __forceinline__ void split1(float y, __nv_bfloat16& h, __nv_bfloat16& l) {
    h = __float2bfloat16(y);
    l = __float2bfloat16(y - __bfloat162float(h));
}

// apply BN+relu, write bf16 hi/lo splits
__global__ void bn_apply_split(const float* __restrict__ X, long total4, int C4,
                               const float* __restrict__ scale, const float* __restrict__ shift,
                               __nv_bfloat16* __restrict__ H, __nv_bfloat16* __restrict__ L) {
    long i = (long)blockIdx.x * blockDim.x + threadIdx.x;
    if (i >= total4) return;
    int c4 = (int)(i % C4) * 4;
    float4 v = ((const float4*)X)[i];
    float y0 = fmaxf(v.x * scale[c4 + 0] + shift[c4 + 0], 0.f);
    float y1 = fmaxf(v.y * scale[c4 + 1] + shift[c4 + 1], 0.f);
    float y2 = fmaxf(v.z * scale[c4 + 2] + shift[c4 + 2], 0.f);
    float y3 = fmaxf(v.w * scale[c4 + 3] + shift[c4 + 3], 0.f);
    __nv_bfloat16 h0, l0, h1, l1, h2, l2, h3, l3;
    split1(y0, h0, l0); split1(y1, h1, l1); split1(y2, h2, l2); split1(y3, h3, l3);
    __nv_bfloat162* H2 = (__nv_bfloat162*)H;
    __nv_bfloat162* L2 = (__nv_bfloat162*)L;
    H2[2 * i] = __nv_bfloat162(h0, h1); H2[2 * i + 1] = __nv_bfloat162(h2, h3);
    L2[2 * i] = __nv_bfloat162(l0, l1); L2[2 * i + 1] = __nv_bfloat162(l2, l3);
}

// BN+relu+max over k, write bf16 hi/lo splits (l0 feeding next GEMM)
__global__ void bn_max_split(const float* __restrict__ Z, int C,
                             const float* __restrict__ scale, const float* __restrict__ shift,
                             __nv_bfloat16* __restrict__ H, __nv_bfloat16* __restrict__ L) {
    long total = (long)MPTS * C;
    long i = (long)blockIdx.x * blockDim.x + threadIdx.x;
    if (i >= total) return;
    int c = (int)(i % C);
    long r = i / C;
    const float* p = Z + r * KNN * (long)C + c;
    float sc = scale[c], sh = shift[c];
    float m = 0.f;
#pragma unroll
    for (int k = 0; k < KNN; k++) m = fmaxf(m, fmaxf(fmaf(p[(long)k * C], sc, sh), 0.f));
    __nv_bfloat16 h, l; split1(m, h, l);
    H[i] = h; L[i] = l;
}

// Final: BN+relu+max over k + transpose via 32x33 smem tile, write fp32 out
__global__ void bn_max_tr(const float* __restrict__ Z, float* __restrict__ out, int C,
                          const float* __restrict__ scale, const float* __restrict__ shift) {
    __shared__ float t[32][33];
    int c = blockIdx.x * 32 + threadIdx.x;
    int n = blockIdx.y * 32 + threadIdx.y;
    int b = blockIdx.z;
    const float* p = Z + ((size_t)(b * NN + n) * KNN) * C + c;
    float sc = scale[c], sh = shift[c];
    float m = 0.f;
#pragma unroll
    for (int k = 0; k < KNN; k++) m = fmaxf(m, fmaxf(fmaf(p[(size_t)k * C], sc, sh), 0.f));
    t[threadIdx.y][threadIdx.x] = m;
    __syncthreads();
    out[((size_t)b * C + blockIdx.x * 32 + threadIdx.y) * NN + blockIdx.y * 32 + threadIdx.x] =
        t[threadIdx.x][threadIdx.y];
}

// ======================= weight splits =======================================
__global__ void wsplit(const float* __restrict__ W, int rows, int cols, int ld, int coloff,
                       __nv_bfloat16* __restrict__ H, __nv_bfloat16* __restrict__ L) {
    long total = (long)rows * cols;
    long i = (long)blockIdx.x * blockDim.x + threadIdx.x;
    if (i >= total) return;
    int r = (int)(i / cols), c = (int)(i % cols);
    float x = W[(long)r * ld + coloff + c];
    __nv_bfloat16 h, l; split1(x, h, l);
    H[i] = h; L[i] = l;
}

__global__ void wdiff_split(const float* __restrict__ W, int O, int Ck,
                            __nv_bfloat16* __restrict__ H, __nv_bfloat16* __restrict__ L) {
    long total = (long)O * Ck;
    long i = (long)blockIdx.x * blockDim.x + threadIdx.x;
    if (i >= total) return;
    int o = (int)(i / Ck), d = (int)(i % Ck);
    float x = W[(long)o * 2 * Ck + Ck + d] - W[(long)o * 2 * Ck + d];
    __nv_bfloat16 h, l; split1(x, h, l);
    H[i] = h; L[i] = l;
}

// ======================= kNN (k=8 incl. self) ================================
__global__ void knn_kernel(const float* __restrict__ xyz, int* __restrict__ idx) {
    int b = blockIdx.x;
    __shared__ float sx[NN], sy[NN], sz[NN];
    const float* base = xyz + (long)b * NN * 3;
    for (int i = threadIdx.x; i < NN; i += blockDim.x) {
        sx[i] = base[i * 3 + 0];
        sy[i] = base[i * 3 + 1];
        sz[i] = base[i * 3 + 2];
    }
    __syncthreads();
    int q = blockIdx.y * 256 + threadIdx.x;
    float qx = sx[q], qy = sy[q], qz = sz[q];
    float bd[KNN]; int bi[KNN];
#pragma unroll
    for (int t = 0; t < KNN; t++) { bd[t] = 3.0e38f; bi[t] = 0; }
    for (int j = 0; j < NN; j++) {
        float dx = sx[j] - qx, dy = sy[j] - qy, dz = sz[j] - qz;
        float d = dx * dx + dy * dy + dz * dz;
        if (d < bd[KNN - 1]) {
            int p = KNN - 1;
#pragma unroll
            for (int t = 0; t < KNN - 1; t++) {
                if (p > 0 && d < bd[p - 1]) { bd[p] = bd[p - 1]; bi[p] = bi[p - 1]; p--; }
            }
            bd[p] = d; bi[p] = j;
        }
    }
#pragma unroll
    for (int t = 0; t < KNN; t++) idx[(b * NN + q) * KNN + t] = bi[t];
}

// ---------------- y[b,n,k,:] = U[b, idx[b,n,k], :] + V[b,n,:] ----------------
__global__ void gather_add(const float* __restrict__ U, const float* __restrict__ V,
                           const int* __restrict__ idx, float* __restrict__ Y, int C) {
    int C4 = C >> 2;
    long total = (long)MBIG * C4;
    long i = (long)blockIdx.x * blockDim.x + threadIdx.x;
    if (i >= total) return;
    int c4 = (int)(i % C4);
    long r = i / C4;
    long bn = r >> 3;
    int b = (int)(bn >> 10);
    int j = idx[r];
    float4 u = ((const float4*)U)[((long)(b * NN + j)) * C4 + c4];
    float4 v = ((const float4*)V)[bn * C4 + c4];
    float4 o; o.x = u.x + v.x; o.y = u.y + v.y; o.z = u.z + v.z; o.w = u.w + v.w;
    ((float4*)Y)[i] = o;
}

// ======================= host orchestration ==================================
extern "C" void kernel_launch(void* const* d_in, const int* in_sizes, int n_in,
                              void* d_out, int out_size) {
    const float* xyz = (const float*)d_in[0];
    const float* W1  = (const float*)d_in[1];
    const float* g1  = (const float*)d_in[2];
    const float* b1  = (const float*)d_in[3];
    const float* W2  = (const float*)d_in[4];
    const float* g2  = (const float*)d_in[5];
    const float* b2  = (const float*)d_in[6];
    const float* WA1 = (const float*)d_in[7];
    const float* gA1 = (const float*)d_in[8];
    const float* bA1 = (const float*)d_in[9];
    const float* WA2 = (const float*)d_in[10];
    const float* gA2 = (const float*)d_in[11];
    const float* bA2 = (const float*)d_in[12];
    const float* WB1 = (const float*)d_in[13];
    const float* gB1 = (const float*)d_in[14];
    const float* bB1 = (const float*)d_in[15];
    const float* WB2 = (const float*)d_in[16];
    const float* gB2 = (const float*)d_in[17];
    const float* bB2 = (const float*)d_in[18];
    float* out = (float*)d_out;

    float *U, *V, *Y, *Z, *scale, *shift, *ps, *ps2;
    __nv_bfloat16 *aH, *aL, *wH, *wL;
    int* idx;
    cudaGetSymbolAddress((void**)&U, g_U);
    cudaGetSymbolAddress((void**)&V, g_V);
    cudaGetSymbolAddress((void**)&Y, g_Y);
    cudaGetSymbolAddress((void**)&Z, g_Z);
    cudaGetSymbolAddress((void**)&aH, g_aH);
    cudaGetSymbolAddress((void**)&aL, g_aL);
    cudaGetSymbolAddress((void**)&wH, g_wH);
    cudaGetSymbolAddress((void**)&wL, g_wL);
    cudaGetSymbolAddress((void**)&idx, g_idx);
    cudaGetSymbolAddress((void**)&scale, g_scale);
    cudaGetSymbolAddress((void**)&shift, g_shift);
    cudaGetSymbolAddress((void**)&ps, g_ps);
    cudaGetSymbolAddress((void**)&ps2, g_ps2);

    auto gemm32 = [&](const float* A, int lda, const float* Bw, int ldb,
                      float* Cm, int M, int K, int Nc) {
        dim3 gs((Nc + 127) / 128, (M + 127) / 128);
        sgemm_nt<<<gs, 256>>>(A, lda, Bw, ldb, Cm, M, K, Nc);
    };
    auto gemmtc = [&](const __nv_bfloat16* Ahh, const __nv_bfloat16* All,
                      const __nv_bfloat16* Bhh, const __nv_bfloat16* Bll,
                      float* Cm, int M, int K, int Nc) {
        dim3 gs(Nc / 128, M / 128);
        gemm_mma<<<gs, 256>>>(Ahh, All, Bhh, Bll, Cm, M, K, Nc);
    };
    auto stats = [&](const float* X, int M, int C, const float* gm, const float* bt) {
        zero2<<<(C + 255) / 256, 256>>>(ps, ps2, C);
        dim3 bs(32, 8), gs(C / 32, 32);
        bn_stats_partial<<<gs, bs>>>(X, M, C, ps, ps2);
        bn_finalize<<<(C + 255) / 256, 256>>>(M, C, ps, ps2, gm, bt, scale, shift);
    };

    // Layer 1: (8192,3)@W1^T -> Y(:,64); BN+relu fp32 in place
    gemm32(xyz, 3, W1, 3, Y, MPTS, 3, 64);
    stats(Y, MPTS, 64, g1, b1);
    {
        long t4 = (long)MPTS * 64 / 4;
        bn_apply_relu<<<(unsigned)((t4 + 255) / 256), 256>>>(Y, t4, 16, scale, shift);
    }
    // Layer 2: h1@W2^T -> Z(:,256); BN+relu -> bf16 splits (h2)
    gemm32(Y, 64, W2, 64, Z, MPTS, 64, 256);
    stats(Z, MPTS, 256, g2, b2);
    {
        long t4 = (long)MPTS * 256 / 4;
        bn_apply_split<<<(unsigned)((t4 + 255) / 256), 256>>>(Z, t4, 64, scale, shift, aH, aL);
    }

    // kNN indices
    {
        dim3 gs(BB, 4);
        knn_kernel<<<gs, 256>>>(xyz, idx);
    }

    // ---- local_op A ----
    wsplit<<<(512 * 256 + 255) / 256, 256>>>(WA1, 512, 256, 512, 0, wH, wL);
    gemmtc(aH, aL, wH, wL, U, MPTS, 256, 512);
    wdiff_split<<<(512 * 256 + 255) / 256, 256>>>(WA1, 512, 256, wH, wL);
    gemmtc(aH, aL, wH, wL, V, MPTS, 256, 512);
    {
        long t4 = (long)MBIG * 512 / 4;
        gather_add<<<(unsigned)((t4 + 255) / 256), 256>>>(U, V, idx, Y, 512);
    }
    stats(Y, MBIG, 512, gA1, bA1);
    {
        long t4 = (long)MBIG * 512 / 4;
        bn_apply_split<<<(unsigned)((t4 + 255) / 256), 256>>>(Y, t4, 128, scale, shift, aH, aL);
    }
    wsplit<<<(512 * 512 + 255) / 256, 256>>>(WA2, 512, 512, 512, 0, wH, wL);
    gemmtc(aH, aL, wH, wL, Z, MBIG, 512, 512);
    stats(Z, MBIG, 512, gA2, bA2);
    {
        long t = (long)MPTS * 512;
        bn_max_split<<<(unsigned)((t + 255) / 256), 256>>>(Z, 512, scale, shift, aH, aL);
    }

    // ---- local_op B ----
    wsplit<<<(1024 * 512 + 255) / 256, 256>>>(WB1, 1024, 512, 1024, 0, wH, wL);
    gemmtc(aH, aL, wH, wL, U, MPTS, 512, 1024);
    wdiff_split<<<(1024 * 512 + 255) / 256, 256>>>(WB1, 1024, 512, wH, wL);
    gemmtc(aH, aL, wH, wL, V, MPTS, 512, 1024);
    {
        long t4 = (long)MBIG * 1024 / 4;
        gather_add<<<(unsigned)((t4 + 255) / 256), 256>>>(U, V, idx, Y, 1024);
    }
    stats(Y, MBIG, 1024, gB1, bB1);
    {
        long t4 = (long)MBIG * 1024 / 4;
        bn_apply_split<<<(unsigned)((t4 + 255) / 256), 256>>>(Y, t4, 256, scale, shift, aH, aL);
    }
    wsplit<<<(1024 * 1024 + 255) / 256, 256>>>(WB2, 1024, 1024, 1024, 0, wH, wL);
    gemmtc(aH, aL, wH, wL, Z, MBIG, 1024, 1024);
    stats(Z, MBIG, 1024, gB2, bB2);
    {
        dim3 bs(32, 32), gs(1024 / 32, NN / 32, BB);
        bn_max_tr<<<gs, bs>>>(Z, out, 1024, scale, shift);
    }
}